// round 1
// baseline (speedup 1.0000x reference)
#include <cuda_runtime.h>
#include <cuda_bf16.h>

#define B_ 2048
#define S_ 277
#define R_ 80
#define L_ 12
#define Z_ 56
#define NROWS (B_ * S_)
#define VCHUNK 16

__device__ double g_bce;
__device__ float  g_var[Z_ * Z_];
__device__ float  g_avg[Z_];

__global__ void zero_kernel() {
    int t = threadIdx.x;
    if (t == 0) g_bce = 0.0;
    for (int i = t; i < Z_ * Z_; i += blockDim.x) g_var[i] = 0.f;
    if (t < Z_) g_avg[t] = 0.f;
}

// One warp per (b,s) row of R_=80 elements.
// x is one-hot: BCE row term = log(out[true]) + sum_{r!=true, out>0} log1p(-out[r])
__global__ void __launch_bounds__(256) bce_kernel(
    const float* __restrict__ x,
    const float* __restrict__ rx,
    const float* __restrict__ masks,
    const int*   __restrict__ lhs)
{
    __shared__ float smask[L_ * R_];
    __shared__ int   slhs[R_];
    for (int i = threadIdx.x; i < L_ * R_; i += blockDim.x) smask[i] = masks[i];
    if (threadIdx.x < R_) slhs[threadIdx.x] = lhs[threadIdx.x];
    __syncthreads();

    const int lane   = threadIdx.x & 31;
    const int gwarp  = (blockIdx.x * blockDim.x + threadIdx.x) >> 5;
    const int nwarps = (gridDim.x * blockDim.x) >> 5;

    float acc = 0.f;
    for (int row = gwarp; row < NROWS; row += nwarps) {
        const size_t base = (size_t)row * R_;
        float x0 = x[base + lane];
        float x1 = x[base + lane + 32];
        float r0 = rx[base + lane];
        float r1 = rx[base + lane + 32];
        float x2 = 0.f, r2 = 0.f;
        if (lane < 16) {
            x2 = x[base + lane + 64];
            r2 = rx[base + lane + 64];
        }
        // argmax of one-hot row
        int tr = -1;
        if (x0 > 0.5f) tr = lane;
        if (x1 > 0.5f) tr = lane + 32;
        if (x2 > 0.5f) tr = lane + 64;
        #pragma unroll
        for (int o = 16; o; o >>= 1) tr = max(tr, __shfl_xor_sync(0xffffffffu, tr, o));

        const int lbase = slhs[tr] * R_;
        float p0 = r0 * smask[lbase + lane];
        float p1 = r1 * smask[lbase + lane + 32];
        float p2 = (lane < 16) ? r2 * smask[lbase + lane + 64] : 0.f;

        float s = p0 + p1 + p2;
        #pragma unroll
        for (int o = 16; o; o >>= 1) s += __shfl_xor_sync(0xffffffffu, s, o);
        const float inv = 1.f / s;

        float o0 = p0 * inv, o1 = p1 * inv, o2 = p2 * inv;
        float t = 0.f;
        t += (lane == tr)      ? fmaxf(logf(o0), -100.f)
                               : (p0 > 0.f ? fmaxf(log1pf(-o0), -100.f) : 0.f);
        t += (lane + 32 == tr) ? fmaxf(logf(o1), -100.f)
                               : (p1 > 0.f ? fmaxf(log1pf(-o1), -100.f) : 0.f);
        if (lane < 16)
            t += (lane + 64 == tr) ? fmaxf(logf(o2), -100.f)
                                   : (p2 > 0.f ? fmaxf(log1pf(-o2), -100.f) : 0.f);
        acc += t;
    }

    #pragma unroll
    for (int o = 16; o; o >>= 1) acc += __shfl_xor_sync(0xffffffffu, acc, o);
    if (lane == 0) atomicAdd(&g_bce, (double)acc);
}

__global__ void __launch_bounds__(256) var_kernel(const float* __restrict__ mu) {
    __shared__ float smu[VCHUNK * Z_];
    const int b0 = blockIdx.x * VCHUNK;
    for (int i = threadIdx.x; i < VCHUNK * Z_; i += blockDim.x)
        smu[i] = mu[(size_t)b0 * Z_ + i];
    __syncthreads();

    if (threadIdx.x < Z_) {
        float s = 0.f;
        #pragma unroll
        for (int b = 0; b < VCHUNK; b++) s += smu[b * Z_ + threadIdx.x];
        atomicAdd(&g_avg[threadIdx.x], s);
    }
    for (int p = threadIdx.x; p < Z_ * Z_; p += blockDim.x) {
        const int i = p / Z_, j = p % Z_;
        float s = 0.f;
        #pragma unroll
        for (int b = 0; b < VCHUNK; b++) s += smu[b * Z_ + i] * smu[b * Z_ + j];
        atomicAdd(&g_var[p], s);
    }
}

__global__ void __launch_bounds__(256) final_kernel(float* __restrict__ out) {
    __shared__ float red[256];
    const int t = threadIdx.x;

    float contrib = 0.f;
    for (int p = t; p < Z_ * Z_; p += 256) {
        const float v = g_var[p] * (1.0f / B_) - ((p / Z_ == p % Z_) ? 1.0f : 0.0f);
        contrib += fabsf(v) * (1.0f / (Z_ * (float)Z_));
    }
    if (t < Z_) {
        const float m = g_avg[t] * (1.0f / B_);
        contrib += m * m * (1.0f / Z_);
    }
    red[t] = contrib;
    __syncthreads();
    for (int o = 128; o; o >>= 1) {
        if (t < o) red[t] += red[t + o];
        __syncthreads();
    }
    if (t == 0) {
        const double bce = -g_bce / (double)((double)S_ * (double)B_);
        out[0] = (float)(bce + (double)red[0]);
    }
}

extern "C" void kernel_launch(void* const* d_in, const int* in_sizes, int n_in,
                              void* d_out, int out_size) {
    const float* x     = (const float*)d_in[0];
    const float* rx    = (const float*)d_in[1];
    const float* mu    = (const float*)d_in[2];
    // d_in[3] = log_var (unused by the reference)
    const float* masks = (const float*)d_in[4];
    const int*   lhs   = (const int*)d_in[5];
    float* out = (float*)d_out;

    zero_kernel<<<1, 256>>>();
    bce_kernel<<<1184, 256>>>(x, rx, masks, lhs);
    var_kernel<<<B_ / VCHUNK, 256>>>(mu);
    final_kernel<<<1, 256>>>(out);
}

// round 2
// speedup vs baseline: 1.8006x; 1.8006x over previous
#include <cuda_runtime.h>
#include <cuda_bf16.h>

#define B_ 2048
#define S_ 277
#define R_ 80
#define L_ 12
#define Z_ 56
#define NROWS (B_ * S_)
#define VBLOCKS 64
#define VCHUNK (B_ / VBLOCKS)   // 32
#define TPB 256
#define FULL 0xffffffffu

__device__ double g_bce;
__device__ float  g_var[Z_ * Z_];
__device__ float  g_avg[Z_];
__device__ unsigned g_ticket;

__global__ void __launch_bounds__(TPB) mega_kernel(
    const float* __restrict__ x,
    const float* __restrict__ rx,
    const float* __restrict__ mu,
    const float* __restrict__ masks,
    const int*   __restrict__ lhs,
    float* __restrict__ out)
{
    __shared__ float smem_buf[VCHUNK * Z_];   // var tile / final reduce
    __shared__ float smask[L_ * R_];
    __shared__ int   slhs[R_];
    __shared__ float swacc[TPB / 32];
    __shared__ bool  s_last;

    const int tid = threadIdx.x;
    const int bid = blockIdx.x;

    if (bid < VBLOCKS) {
        // ---------------- var path: partial mu^T mu and column sums -------
        const int b0 = bid * VCHUNK;
        for (int i = tid; i < VCHUNK * Z_; i += TPB)
            smem_buf[i] = mu[(size_t)b0 * Z_ + i];
        __syncthreads();
        if (tid < Z_) {
            float s = 0.f;
            #pragma unroll
            for (int b = 0; b < VCHUNK; b++) s += smem_buf[b * Z_ + tid];
            atomicAdd(&g_avg[tid], s);
        }
        for (int p = tid; p < Z_ * Z_; p += TPB) {
            const int i = p / Z_, j = p % Z_;
            float s = 0.f;
            #pragma unroll
            for (int b = 0; b < VCHUNK; b++)
                s += smem_buf[b * Z_ + i] * smem_buf[b * Z_ + j];
            atomicAdd(&g_var[p], s);
        }
    } else {
        // ---------------- bce path: warp per (b,s) row ---------------------
        for (int i = tid; i < L_ * R_; i += TPB) smask[i] = masks[i];
        if (tid < R_) slhs[tid] = lhs[tid];
        __syncthreads();

        const int lane = tid & 31;
        const int warp = tid >> 5;
        const int gw   = (bid - VBLOCKS) * (TPB / 32) + warp;
        const int nw   = (gridDim.x - VBLOCKS) * (TPB / 32);

        float acc = 0.f;
        int row = gw;
        float cx0 = 0.f, cx1 = 0.f, cx2 = 0.f, cr0 = 0.f, cr1 = 0.f, cr2 = 0.f;
        if (row < NROWS) {
            const float* xb = x  + (size_t)row * R_;
            const float* rb = rx + (size_t)row * R_;
            cx0 = __ldcs(xb + lane);      cx1 = __ldcs(xb + lane + 32);
            cr0 = __ldcs(rb + lane);      cr1 = __ldcs(rb + lane + 32);
            cx2 = (lane < 16) ? __ldcs(xb + lane + 64) : 0.f;
            cr2 = (lane < 16) ? __ldcs(rb + lane + 64) : 0.f;
        }

        for (; row < NROWS; row += nw) {
            const float x0 = cx0, x1 = cx1, x2 = cx2;
            const float r0 = cr0, r1 = cr1, r2 = cr2;

            const int nrow = row + nw;               // prefetch next row
            if (nrow < NROWS) {
                const float* xb = x  + (size_t)nrow * R_;
                const float* rb = rx + (size_t)nrow * R_;
                cx0 = __ldcs(xb + lane);  cx1 = __ldcs(xb + lane + 32);
                cr0 = __ldcs(rb + lane);  cr1 = __ldcs(rb + lane + 32);
                cx2 = (lane < 16) ? __ldcs(xb + lane + 64) : 0.f;
                cr2 = (lane < 16) ? __ldcs(rb + lane + 64) : 0.f;
            }

            // argmax of one-hot x via ballots
            const unsigned b0 = __ballot_sync(FULL, x0 > 0.5f);
            const unsigned b1 = __ballot_sync(FULL, x1 > 0.5f);
            const unsigned b2 = __ballot_sync(FULL, x2 > 0.5f);
            const int tr = b0 ? (__ffs(b0) - 1)
                              : (b1 ? (31 + __ffs(b1)) : (63 + __ffs(b2)));

            const float* mrow = smask + slhs[tr] * R_;
            const float p0 = r0 * mrow[lane];
            const float p1 = r1 * mrow[lane + 32];
            const float p2 = (lane < 16) ? r2 * mrow[lane + 64] : 0.f;

            // row sum
            float s = p0 + p1 + p2;
            #pragma unroll
            for (int o = 16; o; o >>= 1) s += __shfl_xor_sync(FULL, s, o);
            const float inv = __fdividef(1.0f, s);

            // product of (1 - o_r) over r != tr  (masked p=0 gives factor 1)
            const float f0 = (tr == lane)      ? 1.f : fmaf(-p0, inv, 1.f);
            const float f1 = (tr == lane + 32) ? 1.f : fmaf(-p1, inv, 1.f);
            const float f2 = (tr == lane + 64) ? 1.f : fmaf(-p2, inv, 1.f);
            float pr = f0 * f1 * f2;
            #pragma unroll
            for (int o = 16; o; o >>= 1) pr *= __shfl_xor_sync(FULL, pr, o);

            // p_true via one shuffle from its owning lane
            const float cand = (tr < 32) ? p0 : ((tr < 64) ? p1 : p2);
            const float pt = __shfl_sync(FULL, cand, tr & 31);

            acc += __logf(pt * inv * pr);   // log(o_tr) + sum log(1-o_r)
        }

        if (lane == 0) swacc[warp] = acc;
        __syncthreads();
        if (tid == 0) {
            float t = 0.f;
            #pragma unroll
            for (int w = 0; w < TPB / 32; w++) t += swacc[w];
            atomicAdd(&g_bce, (double)t);
        }
    }

    // ---------------- ticket + last-block finalize -------------------------
    __threadfence();
    __syncthreads();
    if (tid == 0) {
        const unsigned t = atomicAdd(&g_ticket, 1u);
        s_last = (t == gridDim.x - 1);
    }
    __syncthreads();
    if (!s_last) return;
    __threadfence();

    float contrib = 0.f;
    for (int p = tid; p < Z_ * Z_; p += TPB) {
        const float v = fmaf(g_var[p], 1.0f / B_,
                             ((p / Z_) == (p % Z_)) ? -1.0f : 0.0f);
        contrib += fabsf(v);
        g_var[p] = 0.f;                         // reset for next replay
    }
    contrib *= 1.0f / ((float)Z_ * (float)Z_);
    if (tid < Z_) {
        const float m = g_avg[tid] * (1.0f / B_);
        contrib += m * m * (1.0f / Z_);
        g_avg[tid] = 0.f;
    }
    smem_buf[tid] = contrib;
    __syncthreads();
    for (int o = TPB / 2; o; o >>= 1) {
        if (tid < o) smem_buf[tid] += smem_buf[tid + o];
        __syncthreads();
    }
    if (tid == 0) {
        const double bce = -g_bce / ((double)S_ * (double)B_);
        out[0] = (float)(bce + (double)smem_buf[0]);
        g_bce = 0.0;
        g_ticket = 0u;
    }
}

extern "C" void kernel_launch(void* const* d_in, const int* in_sizes, int n_in,
                              void* d_out, int out_size) {
    const float* x     = (const float*)d_in[0];
    const float* rx    = (const float*)d_in[1];
    const float* mu    = (const float*)d_in[2];
    // d_in[3] = log_var (unused by the reference)
    const float* masks = (const float*)d_in[4];
    const int*   lhs   = (const int*)d_in[5];
    float* out = (float*)d_out;

    int dev = 0;
    cudaGetDevice(&dev);
    int sms = 148;
    cudaDeviceGetAttribute(&sms, cudaDevAttrMultiProcessorCount, dev);
    int nb = 0;
    cudaOccupancyMaxActiveBlocksPerMultiprocessor(&nb, mega_kernel, TPB, 0);
    if (nb < 1) nb = 1;
    int grid = sms * nb;                 // exactly one resident wave
    if (grid < VBLOCKS + sms) grid = VBLOCKS + sms;

    mega_kernel<<<grid, TPB>>>(x, rx, mu, masks, lhs, out);
}

// round 3
// speedup vs baseline: 1.8482x; 1.0264x over previous
#include <cuda_runtime.h>
#include <cuda_bf16.h>

#define B_ 2048
#define S_ 277
#define R_ 80
#define L_ 12
#define Z_ 56
#define NROWS (B_ * S_)
#define VBLOCKS 64
#define VCHUNK (B_ / VBLOCKS)   // 32
#define TPB 256
#define WPB (TPB / 32)
#define FULL 0xffffffffu
#define R4 (R_ / 4)              // 20 float4 per row

__device__ double g_bce;
__device__ float  g_var[Z_ * Z_];
__device__ float  g_avg[Z_];
__device__ unsigned g_ticket;

__global__ void __launch_bounds__(TPB) mega_kernel(
    const float* __restrict__ x,
    const float* __restrict__ rx,
    const float* __restrict__ mu,
    const float* __restrict__ masks,
    const int*   __restrict__ lhs,
    float* __restrict__ out)
{
    __shared__ float  smem_buf[VCHUNK * Z_];      // var tile / final reduce
    __shared__ float4 smask4[L_ * R4];            // masks as float4
    __shared__ int    slhs[128];                  // padded (safe garbage index)
    __shared__ float  swacc[WPB];
    __shared__ bool   s_last;

    const int tid = threadIdx.x;
    const int bid = blockIdx.x;

    // masks + lhs into smem (all blocks)
    {
        const float4* m4 = (const float4*)masks;
        for (int i = tid; i < L_ * R4; i += TPB) smask4[i] = m4[i];
        if (tid < 128) slhs[tid] = (tid < R_) ? lhs[tid] : 0;
    }
    __syncthreads();

    // ---------------- var path: first VBLOCKS blocks do mu^T mu tile ------
    if (bid < VBLOCKS) {
        const int b0 = bid * VCHUNK;
        for (int i = tid; i < VCHUNK * Z_; i += TPB)
            smem_buf[i] = mu[(size_t)b0 * Z_ + i];
        __syncthreads();
        if (tid < Z_) {
            float s = 0.f;
            #pragma unroll
            for (int b = 0; b < VCHUNK; b++) s += smem_buf[b * Z_ + tid];
            atomicAdd(&g_avg[tid], s);
        }
        for (int p = tid; p < Z_ * Z_; p += TPB) {
            const int i = p / Z_, j = p % Z_;
            float s = 0.f;
            #pragma unroll
            for (int b = 0; b < VCHUNK; b++)
                s += smem_buf[b * Z_ + i] * smem_buf[b * Z_ + j];
            atomicAdd(&g_var[p], s);
        }
    }

    // ---------------- bce path: warp per row, float4 lanes 0..19 ----------
    const int lane = tid & 31;
    const int warp = tid >> 5;
    const int gw   = bid * WPB + warp;
    const int nw   = gridDim.x * WPB;
    const bool act = (lane < R4);

    float acc = 0.f;
    int row = gw;
    float4 cx = {0,0,0,0}, cr = {0,0,0,0};
    if (row < NROWS && act) {
        cx = __ldcs((const float4*)(x  + (size_t)row * R_) + lane);
        cr = __ldcs((const float4*)(rx + (size_t)row * R_) + lane);
    }

    for (; row < NROWS; row += nw) {
        const float4 xv = cx, rv = cr;

        const int nrow = row + nw;                 // prefetch next row
        if (nrow < NROWS && act) {
            cx = __ldcs((const float4*)(x  + (size_t)nrow * R_) + lane);
            cr = __ldcs((const float4*)(rx + (size_t)nrow * R_) + lane);
        }

        // one-hot argmax: owner lane + local offset j
        const bool h0 = xv.x > 0.5f, h1 = xv.y > 0.5f,
                   h2 = xv.z > 0.5f, h3 = xv.w > 0.5f;
        const unsigned bal = __ballot_sync(FULL, h0 | h1 | h2 | h3);
        const int owner = __ffs(bal) - 1;
        const int j = h1 ? 1 : (h2 ? 2 : (h3 ? 3 : 0));     // valid on owner
        int lrow = slhs[(4 * lane + j) & 127];              // safe on all lanes
        lrow = __shfl_sync(FULL, lrow, owner);

        // masked probs
        const float4 m = smask4[lrow * R4 + (act ? lane : 0)];
        const float p0 = act ? rv.x * m.x : 0.f;
        const float p1 = act ? rv.y * m.y : 0.f;
        const float p2 = act ? rv.z * m.z : 0.f;
        const float p3 = act ? rv.w * m.w : 0.f;

        // row sum
        float s = (p0 + p1) + (p2 + p3);
        #pragma unroll
        for (int o = 16; o; o >>= 1) s += __shfl_xor_sync(FULL, s, o);
        const float inv = __fdividef(1.0f, s);

        // product of (1 - o_r), excluding the true rule (owner-local)
        float f0 = fmaf(-p0, inv, 1.f);
        float f1 = fmaf(-p1, inv, 1.f);
        float f2 = fmaf(-p2, inv, 1.f);
        float f3 = fmaf(-p3, inv, 1.f);
        float ptl = p0;
        if (lane == owner) {
            if      (j == 0) { f0 = 1.f; ptl = p0; }
            else if (j == 1) { f1 = 1.f; ptl = p1; }
            else if (j == 2) { f2 = 1.f; ptl = p2; }
            else             { f3 = 1.f; ptl = p3; }
        }
        float pr = (f0 * f1) * (f2 * f3);
        #pragma unroll
        for (int o = 16; o; o >>= 1) pr *= __shfl_xor_sync(FULL, pr, o);

        const float pt = __shfl_sync(FULL, ptl, owner);
        acc += __logf(pt * inv * pr);   // log(o_true) + sum log(1 - o_r)
    }

    if (lane == 0) swacc[warp] = acc;
    __syncthreads();
    if (tid == 0) {
        float t = 0.f;
        #pragma unroll
        for (int w = 0; w < WPB; w++) t += swacc[w];
        atomicAdd(&g_bce, (double)t);
    }

    // ---------------- ticket + last-block finalize -------------------------
    __threadfence();
    __syncthreads();
    if (tid == 0) {
        const unsigned t = atomicAdd(&g_ticket, 1u);
        s_last = (t == gridDim.x - 1);
    }
    __syncthreads();
    if (!s_last) return;
    __threadfence();

    float contrib = 0.f;
    for (int p = tid; p < Z_ * Z_; p += TPB) {
        const float v = fmaf(g_var[p], 1.0f / B_,
                             ((p / Z_) == (p % Z_)) ? -1.0f : 0.0f);
        contrib += fabsf(v);
        g_var[p] = 0.f;                          // reset for graph replay
    }
    contrib *= 1.0f / ((float)Z_ * (float)Z_);
    if (tid < Z_) {
        const float m = g_avg[tid] * (1.0f / B_);
        contrib += m * m * (1.0f / Z_);
        g_avg[tid] = 0.f;
    }
    smem_buf[tid] = contrib;
    __syncthreads();
    for (int o = TPB / 2; o; o >>= 1) {
        if (tid < o) smem_buf[tid] += smem_buf[tid + o];
        __syncthreads();
    }
    if (tid == 0) {
        const double bce = -g_bce / ((double)S_ * (double)B_);
        out[0] = (float)(bce + (double)smem_buf[0]);
        g_bce = 0.0;
        g_ticket = 0u;
    }
}

extern "C" void kernel_launch(void* const* d_in, const int* in_sizes, int n_in,
                              void* d_out, int out_size) {
    const float* x     = (const float*)d_in[0];
    const float* rx    = (const float*)d_in[1];
    const float* mu    = (const float*)d_in[2];
    // d_in[3] = log_var (unused by the reference)
    const float* masks = (const float*)d_in[4];
    const int*   lhs   = (const int*)d_in[5];
    float* out = (float*)d_out;

    int dev = 0;
    cudaGetDevice(&dev);
    int sms = 148;
    cudaDeviceGetAttribute(&sms, cudaDevAttrMultiProcessorCount, dev);
    int nb = 0;
    cudaOccupancyMaxActiveBlocksPerMultiprocessor(&nb, mega_kernel, TPB, 0);
    if (nb < 1) nb = 1;
    int grid = sms * nb;                 // exactly one resident wave
    if (grid < VBLOCKS + 1) grid = VBLOCKS + 1;

    mega_kernel<<<grid, TPB>>>(x, rx, mu, masks, lhs, out);
}

// round 4
// speedup vs baseline: 2.4912x; 1.3480x over previous
#include <cuda_runtime.h>
#include <cuda_bf16.h>

#define B_ 2048
#define S_ 277
#define R_ 80
#define L_ 12
#define Z_ 56
#define NROWS (B_ * S_)          // 567296, divisible by 8
#define VBLOCKS 64
#define VCHUNK (B_ / VBLOCKS)    // 32
#define TPB 256
#define WPB (TPB / 32)
#define FULL 0xffffffffu
#define R4 (R_ / 4)              // 20 float4 per row

__device__ double g_bce;
__device__ float  g_var[Z_ * Z_];
__device__ float  g_avg[Z_];
__device__ unsigned g_ticket;

__global__ void __launch_bounds__(TPB) mega_kernel(
    const float* __restrict__ x,
    const float* __restrict__ rx,
    const float* __restrict__ mu,
    const float* __restrict__ masks,
    const int*   __restrict__ lhs,
    float* __restrict__ out)
{
    __shared__ float  smem_buf[VCHUNK * Z_];      // var tile / final reduce
    __shared__ float4 smask4[L_ * R4];
    __shared__ int    slhs[R_];
    __shared__ float  swacc[WPB];
    __shared__ bool   s_last;

    const int tid = threadIdx.x;
    const int bid = blockIdx.x;

    {
        const float4* m4 = (const float4*)masks;
        for (int i = tid; i < L_ * R4; i += TPB) smask4[i] = m4[i];
        if (tid < R_) slhs[tid] = lhs[tid];
    }
    __syncthreads();

    // ---------------- var path: first VBLOCKS blocks do mu^T mu tile ------
    if (bid < VBLOCKS) {
        const int b0 = bid * VCHUNK;
        for (int i = tid; i < VCHUNK * Z_; i += TPB)
            smem_buf[i] = mu[(size_t)b0 * Z_ + i];
        __syncthreads();
        if (tid < Z_) {
            float s = 0.f;
            #pragma unroll
            for (int b = 0; b < VCHUNK; b++) s += smem_buf[b * Z_ + tid];
            atomicAdd(&g_avg[tid], s);
        }
        for (int p = tid; p < Z_ * Z_; p += TPB) {
            const int i = p / Z_, j = p % Z_;
            float s = 0.f;
            #pragma unroll
            for (int b = 0; b < VCHUNK; b++)
                s += smem_buf[b * Z_ + i] * smem_buf[b * Z_ + j];
            atomicAdd(&g_var[p], s);
        }
    }

    // ---------------- bce: 8 rows per warp, 4 lanes per row ----------------
    const int lane = tid & 31;
    const int warp = tid >> 5;
    const int sr   = lane >> 2;          // sub-row 0..7
    const int g    = lane & 3;           // chunk  0..3
    const int gw   = bid * WPB + warp;
    const int nw   = gridDim.x * WPB;

    float acc = 0.f;

    for (int r0 = gw * 8; r0 < NROWS; r0 += nw * 8) {
        const float4* xb = (const float4*)(x  + (size_t)r0 * R_);
        const float4* rb = (const float4*)(rx + (size_t)r0 * R_);
        const int cbase = sr * R4 + g;

        float4 xv[5], rv[5];
        #pragma unroll
        for (int k = 0; k < 5; k++) {
            xv[k] = __ldcs(xb + cbase + 4 * k);
            rv[k] = __ldcs(rb + cbase + 4 * k);
        }

        // tr = sum(x * index), rt = sum(x * r) = p_true (true-rule mask == 1)
        float trp = 0.f, rtp = 0.f;
        #pragma unroll
        for (int k = 0; k < 5; k++) {
            const float i0 = (float)(4 * g + 16 * k);
            trp = fmaf(xv[k].x, i0,       trp);
            trp = fmaf(xv[k].y, i0 + 1.f, trp);
            trp = fmaf(xv[k].z, i0 + 2.f, trp);
            trp = fmaf(xv[k].w, i0 + 3.f, trp);
            rtp = fmaf(xv[k].x, rv[k].x, rtp);
            rtp = fmaf(xv[k].y, rv[k].y, rtp);
            rtp = fmaf(xv[k].z, rv[k].z, rtp);
            rtp = fmaf(xv[k].w, rv[k].w, rtp);
        }
        trp += __shfl_xor_sync(FULL, trp, 1);
        rtp += __shfl_xor_sync(FULL, rtp, 1);
        trp += __shfl_xor_sync(FULL, trp, 2);
        rtp += __shfl_xor_sync(FULL, rtp, 2);

        const int lrow = slhs[__float2int_rn(trp)];

        // p = r*mask; w = p*(1-x) (zero at the true element); s = sum(p)
        float s = 0.f;
        float4 w[5];
        #pragma unroll
        for (int k = 0; k < 5; k++) {
            const float4 m = smask4[lrow * R4 + g + 4 * k];
            float4 p;
            p.x = rv[k].x * m.x;  p.y = rv[k].y * m.y;
            p.z = rv[k].z * m.z;  p.w = rv[k].w * m.w;
            s += (p.x + p.y) + (p.z + p.w);
            w[k].x = fmaf(-p.x, xv[k].x, p.x);
            w[k].y = fmaf(-p.y, xv[k].y, p.y);
            w[k].z = fmaf(-p.z, xv[k].z, p.z);
            w[k].w = fmaf(-p.w, xv[k].w, p.w);
        }
        s += __shfl_xor_sync(FULL, s, 1);
        s += __shfl_xor_sync(FULL, s, 2);
        const float inv = __fdividef(1.0f, s);

        // prod of (1 - o_r) excluding true (w=0 there -> factor 1)
        float pr = 1.f;
        #pragma unroll
        for (int k = 0; k < 5; k++) {
            pr *= fmaf(-w[k].x, inv, 1.f) * fmaf(-w[k].y, inv, 1.f)
                * fmaf(-w[k].z, inv, 1.f) * fmaf(-w[k].w, inv, 1.f);
        }
        pr *= __shfl_xor_sync(FULL, pr, 1);
        pr *= __shfl_xor_sync(FULL, pr, 2);

        // log(o_true) + sum log(1-o_r); identical on all 4 group lanes
        acc += __logf(rtp * inv * pr);
    }

    acc *= 0.25f;                          // each row counted by 4 lanes
    #pragma unroll
    for (int o = 16; o; o >>= 1) acc += __shfl_xor_sync(FULL, acc, o);
    if (lane == 0) swacc[warp] = acc;
    __syncthreads();
    if (tid == 0) {
        float t = 0.f;
        #pragma unroll
        for (int w2 = 0; w2 < WPB; w2++) t += swacc[w2];
        atomicAdd(&g_bce, (double)t);
    }

    // ---------------- ticket + last-block finalize -------------------------
    __threadfence();
    __syncthreads();
    if (tid == 0) {
        const unsigned t = atomicAdd(&g_ticket, 1u);
        s_last = (t == gridDim.x - 1);
    }
    __syncthreads();
    if (!s_last) return;
    __threadfence();

    float contrib = 0.f;
    for (int p = tid; p < Z_ * Z_; p += TPB) {
        const float v = fmaf(g_var[p], 1.0f / B_,
                             ((p / Z_) == (p % Z_)) ? -1.0f : 0.0f);
        contrib += fabsf(v);
        g_var[p] = 0.f;                          // reset for graph replay
    }
    contrib *= 1.0f / ((float)Z_ * (float)Z_);
    if (tid < Z_) {
        const float m = g_avg[tid] * (1.0f / B_);
        contrib += m * m * (1.0f / Z_);
        g_avg[tid] = 0.f;
    }
    smem_buf[tid] = contrib;
    __syncthreads();
    for (int o = TPB / 2; o; o >>= 1) {
        if (tid < o) smem_buf[tid] += smem_buf[tid + o];
        __syncthreads();
    }
    if (tid == 0) {
        const double bce = -g_bce / ((double)S_ * (double)B_);
        out[0] = (float)(bce + (double)smem_buf[0]);
        g_bce = 0.0;
        g_ticket = 0u;
    }
}

extern "C" void kernel_launch(void* const* d_in, const int* in_sizes, int n_in,
                              void* d_out, int out_size) {
    const float* x     = (const float*)d_in[0];
    const float* rx    = (const float*)d_in[1];
    const float* mu    = (const float*)d_in[2];
    // d_in[3] = log_var (unused by the reference)
    const float* masks = (const float*)d_in[4];
    const int*   lhs   = (const int*)d_in[5];
    float* out = (float*)d_out;

    int dev = 0;
    cudaGetDevice(&dev);
    int sms = 148;
    cudaDeviceGetAttribute(&sms, cudaDevAttrMultiProcessorCount, dev);
    int nb = 0;
    cudaOccupancyMaxActiveBlocksPerMultiprocessor(&nb, mega_kernel, TPB, 0);
    if (nb < 1) nb = 1;
    int grid = sms * nb;                 // one resident wave
    if (grid < VBLOCKS + 1) grid = VBLOCKS + 1;

    mega_kernel<<<grid, TPB>>>(x, rx, mu, masks, lhs, out);
}